// round 10
// baseline (speedup 1.0000x reference)
#include <cuda_runtime.h>
#include <cuda_fp16.h>
#include <cstdint>
#include <math.h>

// ---------------------------------------------------------------------------
// Problem constants
// ---------------------------------------------------------------------------
static constexpr int B_ = 8;
static constexpr int K_ = 2048;   // time / contraction dim
static constexpr int D_ = 1024;   // channel dim
static constexpr int CH2 = 32;    // half-chunks (T2 = 64 steps each)
static constexpr int T2 = K_ / CH2;  // 64

// GEMM tiling: C[t, d] = sum_k W[t,k] * x[k,d]   per batch
static constexpr int BM = 128;   // t tile (= 2 half-chunks = 4 quarter-chunks)
static constexpr int BN = 64;    // d tile (small tile -> 2048 CTAs, full waves)
static constexpr int BK = 32;    // k per stage
static constexpr int NSTAGE_IT = K_ / BK;  // 64
static constexpr int NSTAGES = 4;          // pipeline depth

// smem strides (bytes), padded for conflict-free ldmatrix
static constexpr int W_STRIDE = 80;    // 32 fp16 = 64B + 16B pad
static constexpr int X_STRIDE = 144;   // 64 fp16 = 128B + 16B pad
static constexpr int W_TILE_B = BM * W_STRIDE;        // 10240
static constexpr int X_TILE_B = BK * X_STRIDE;        // 4608
static constexpr int STAGE_B = W_TILE_B + X_TILE_B;   // 14848
static constexpr int SMEM_TOTAL = NSTAGES * STAGE_B;  // 59392

// epilogue smem reuse: lam tile [128][72] fp16 (144B rows -> 16B-aligned rows)
static constexpr int LAM_STRIDE = 72;                  // halves (144B rows)
static constexpr int LAM_BYTES = BM * LAM_STRIDE * 2;  // 18432
static constexpr int QSUM_OFF = LAM_BYTES;             // 4*64 float A + U
static_assert(QSUM_OFF + 4 * 64 * 2 * 4 <= SMEM_TOTAL, "epilogue fits");
static_assert((LAM_STRIDE * 2) % 16 == 0, "uint4-aligned lam rows");

// ---------------------------------------------------------------------------
// Device scratch (no cudaMalloc allowed)
// ---------------------------------------------------------------------------
__device__ __align__(256) __half g_Wh[(size_t)K_ * K_];
__device__ __align__(256) __half g_xh[(size_t)B_ * K_ * D_];
__device__ __align__(256) __half g_lam16[(size_t)B_ * K_ * D_];
__device__ __align__(256) float g_A[(size_t)B_ * CH2 * D_];   // half-chunk prod
__device__ __align__(256) float g_U[(size_t)B_ * CH2 * D_];   // half-chunk off

// ---------------------------------------------------------------------------
// PTX helpers (baseline ISA only — target sm_103 has no 'a' features)
// ---------------------------------------------------------------------------
__device__ __forceinline__ uint32_t smem_u32(const void* p) {
    uint32_t a;
    asm("{ .reg .u64 t; cvta.to.shared.u64 t, %1; cvt.u32.u64 %0, t; }"
        : "=r"(a) : "l"(p));
    return a;
}

__device__ __forceinline__ void cp_async16(uint32_t dst, const void* src) {
    asm volatile("cp.async.cg.shared.global [%0], [%1], 16;"
                 :: "r"(dst), "l"(src));
}

__device__ __forceinline__ void ldm_x4(uint32_t* r, uint32_t addr) {
    asm volatile("ldmatrix.sync.aligned.m8n8.x4.shared.b16 {%0,%1,%2,%3}, [%4];"
                 : "=r"(r[0]), "=r"(r[1]), "=r"(r[2]), "=r"(r[3]) : "r"(addr));
}

__device__ __forceinline__ void ldm_x4_t(uint32_t* r, uint32_t addr) {
    asm volatile("ldmatrix.sync.aligned.m8n8.x4.trans.shared.b16 {%0,%1,%2,%3}, [%4];"
                 : "=r"(r[0]), "=r"(r[1]), "=r"(r[2]), "=r"(r[3]) : "r"(addr));
}

__device__ __forceinline__ void mma_f16(float* c, const uint32_t* a,
                                        const uint32_t b0, const uint32_t b1) {
    asm volatile(
        "mma.sync.aligned.m16n8k16.row.col.f32.f16.f16.f32 "
        "{%0,%1,%2,%3}, {%4,%5,%6,%7}, {%8,%9}, {%0,%1,%2,%3};"
        : "+f"(c[0]), "+f"(c[1]), "+f"(c[2]), "+f"(c[3])
        : "r"(a[0]), "r"(a[1]), "r"(a[2]), "r"(a[3]), "r"(b0), "r"(b1));
}

// ---------------------------------------------------------------------------
// Fused converter: fp32 -> fp16 for W (4M elems) then x (16M elems)
// ---------------------------------------------------------------------------
__global__ void convert_all_kernel(const float* __restrict__ W,
                                   const float* __restrict__ x) {
    const size_t gi = ((size_t)blockIdx.x * blockDim.x + threadIdx.x) * 4;
    const size_t WN = (size_t)K_ * K_;
    const float* src;
    __half* dst;
    size_t i;
    if (gi < WN) {
        src = W; dst = g_Wh; i = gi;
    } else {
        src = x; dst = g_xh; i = gi - WN;
    }
    float4 v = *reinterpret_cast<const float4*>(src + i);
    __half h[4];
    h[0] = __float2half(v.x); h[1] = __float2half(v.y);
    h[2] = __float2half(v.z); h[3] = __float2half(v.w);
    *reinterpret_cast<uint2*>(dst + i) = *reinterpret_cast<uint2*>(h);
}

// ---------------------------------------------------------------------------
// GEMM + sigmoid + fused quarter->half scan summaries (lam stored fp16)
// 128(M=t) x 64(N=d) tile, 8 warps (2 M x 4 N), warp tile 64x16.
// ---------------------------------------------------------------------------
__device__ __forceinline__ void load_stage(uint32_t sbase,
                                           const __half* Wp,
                                           const __half* xp,
                                           int k0, int tid) {
    // W tile: 128 rows x 4 segs of 16B = 512 units
    #pragma unroll
    for (int u = tid; u < 512; u += 256) {
        const int row = u >> 2, seg = u & 3;
        const uint32_t off = (uint32_t)(row * W_STRIDE + seg * 16);
        cp_async16(sbase + off, Wp + (size_t)row * K_ + k0 + seg * 8);
    }
    // x tile: 32 rows x 8 segs of 16B = 256 units
    {
        const int u = tid;
        if (u < 256) {
            const int row = u >> 3, seg = u & 7;
            const uint32_t off = (uint32_t)(row * X_STRIDE + seg * 16);
            cp_async16(sbase + W_TILE_B + off,
                       xp + (size_t)(k0 + row) * D_ + seg * 8);
        }
    }
    asm volatile("cp.async.commit_group;" ::: "memory");
}

__global__ __launch_bounds__(256, 2)
void gemm_sigmoid_kernel(const float* __restrict__ bias) {
    extern __shared__ char smem[];
    const uint32_t sb = smem_u32(smem);
    const int tid = threadIdx.x;
    const int lane = tid & 31;
    const int warp = tid >> 5;
    const int wm = warp >> 2;          // 0..1  (64 rows each)
    const int wn = warp & 3;           // 0..3  (16 cols each)

    const int d0 = blockIdx.x * BN;
    const int t0 = blockIdx.y * BM;
    const int b = blockIdx.z;

    const __half* Wp = g_Wh + (size_t)t0 * K_;
    const __half* xp = g_xh + (size_t)b * K_ * D_ + d0;

    float acc[4][2][4];
    #pragma unroll
    for (int i = 0; i < 4; i++)
        #pragma unroll
        for (int j = 0; j < 2; j++)
            #pragma unroll
            for (int q = 0; q < 4; q++) acc[i][j][q] = 0.0f;

    const int a_row_in = (lane & 15);
    const int a_kseg = (lane >> 4);
    const int b_krow = (lane & 15);
    const int b_nseg = (lane >> 4);

    #pragma unroll
    for (int p = 0; p < NSTAGES - 1; p++)
        load_stage(sb + p * STAGE_B, Wp, xp, p * BK, tid);

    for (int c = 0; c < NSTAGE_IT; c++) {
        asm volatile("cp.async.wait_group %0;" :: "n"(NSTAGES - 2) : "memory");
        __syncthreads();

        if (c + NSTAGES - 1 < NSTAGE_IT)
            load_stage(sb + ((c + NSTAGES - 1) % NSTAGES) * STAGE_B,
                       Wp, xp, (c + NSTAGES - 1) * BK, tid);
        else
            asm volatile("cp.async.commit_group;" ::: "memory");

        const uint32_t st = sb + (c % NSTAGES) * STAGE_B;
        const uint32_t sW = st;
        const uint32_t sX = st + W_TILE_B;

        #pragma unroll
        for (int kk = 0; kk < 2; kk++) {
            uint32_t af[4][4];
            #pragma unroll
            for (int i = 0; i < 4; i++) {
                const uint32_t aoff =
                    (uint32_t)((wm * 64 + i * 16 + a_row_in) * W_STRIDE +
                               kk * 32 + a_kseg * 16);
                ldm_x4(af[i], sW + aoff);
            }
            uint32_t bf[4];
            {
                const uint32_t boff =
                    (uint32_t)((kk * 16 + b_krow) * X_STRIDE +
                               (wn * 16 + b_nseg * 8) * 2);
                ldm_x4_t(bf, sX + boff);
            }
            #pragma unroll
            for (int i = 0; i < 4; i++) {
                #pragma unroll
                for (int j2 = 0; j2 < 2; j2++) {
                    mma_f16(acc[i][j2], af[i], bf[j2 * 2], bf[j2 * 2 + 1]);
                }
            }
        }
    }

    // drain async engine before smem reuse
    asm volatile("cp.async.wait_group 0;" ::: "memory");
    __syncthreads();

    // ---- Epilogue phase 1: bias + sigmoid -> fp16 lam tile in smem ----
    __half* lamS = reinterpret_cast<__half*>(smem);          // [128][72]
    const int gr = lane >> 2;
    const int gc = (lane & 3) * 2;
    #pragma unroll
    for (int i = 0; i < 4; i++) {
        const int tr0 = wm * 64 + i * 16 + gr;
        const float bz0 = __ldg(&bias[t0 + tr0]);
        const float bz1 = __ldg(&bias[t0 + tr0 + 8]);
        #pragma unroll
        for (int j2 = 0; j2 < 2; j2++) {
            const int dc = wn * 16 + j2 * 8 + gc;
            __half2 h0, h1;
            h0.x = __float2half(1.0f / (1.0f + __expf(-(acc[i][j2][0] + bz0))));
            h0.y = __float2half(1.0f / (1.0f + __expf(-(acc[i][j2][1] + bz0))));
            h1.x = __float2half(1.0f / (1.0f + __expf(-(acc[i][j2][2] + bz1))));
            h1.y = __float2half(1.0f / (1.0f + __expf(-(acc[i][j2][3] + bz1))));
            *reinterpret_cast<__half2*>(&lamS[tr0 * LAM_STRIDE + dc]) = h0;
            *reinterpret_cast<__half2*>(&lamS[(tr0 + 8) * LAM_STRIDE + dc]) = h1;
        }
    }
    __syncthreads();

    // ---- Epilogue phase 2a: coalesced uint4 store of fp16 lam to gmem ----
    __half* lamB = g_lam16 + ((size_t)b * K_ + t0) * D_ + d0;
    #pragma unroll
    for (int u = tid; u < BM * (BN / 8); u += 256) {  // 1024 uint4
        const int row = u >> 3;          // 0..127
        const int col8 = (u & 7) * 8;    // 0..56
        const uint4 v = *reinterpret_cast<const uint4*>(
            &lamS[row * LAM_STRIDE + col8]);
        *reinterpret_cast<uint4*>(&lamB[(size_t)row * D_ + col8]) = v;
    }

    // ---- Epilogue phase 2b: quarter summaries (32 steps each) ----
    float* qA = reinterpret_cast<float*>(smem + QSUM_OFF);        // [4][64]
    float* qU = qA + 4 * 64;
    {
        const int q = tid >> 6;          // 0..3 quarter
        const int dc = tid & 63;
        const __half* xcol = g_xh +
            ((size_t)b * K_ + t0 + q * 32) * D_ + d0 + dc;
        float A = 1.0f, U = 0.0f;
        #pragma unroll 8
        for (int tt = 0; tt < 32; tt++) {
            const float l = __half2float(lamS[(q * 32 + tt) * LAM_STRIDE + dc]);
            const float xv = __half2float(xcol[(size_t)tt * D_]);
            U = fmaf(l, U - xv, xv);
            A *= l;
        }
        qA[q * 64 + dc] = A;
        qU[q * 64 + dc] = U;
    }
    __syncthreads();

    // ---- Epilogue phase 2c: combine quarter pairs -> half-chunk summaries ----
    if (tid < 128) {
        const int h = tid >> 6;          // 0..1 half
        const int dc = tid & 63;
        const float A0 = qA[(2 * h) * 64 + dc];
        const float U0 = qU[(2 * h) * 64 + dc];
        const float A1 = qA[(2 * h + 1) * 64 + dc];
        const float U1 = qU[(2 * h + 1) * 64 + dc];
        const int c2 = blockIdx.y * 2 + h;
        const size_t idx = ((size_t)b * CH2 + c2) * D_ + d0 + dc;
        g_A[idx] = A1 * A0;
        g_U[idx] = fmaf(A1, U0, U1);
    }
}

// ---------------------------------------------------------------------------
// Scan pass 3: per (b, half-chunk, d-half) block; carry computed in-register
// from half-chunk summaries. 128 threads x float4 over 512 d each.
// fp16 x + fp16 lam reads, unroll-8 for MLP. Heavy blocks launch first.
// ---------------------------------------------------------------------------
__global__ __launch_bounds__(128)
void scan_pass3(float* __restrict__ ys) {
    const int c2 = CH2 - 1 - blockIdx.x;  // heavy blocks first
    const int b = blockIdx.z;
    const int d = blockIdx.y * 512 + threadIdx.x * 4;

    // carry = prefix of (A,U) over half-chunks < c2 (affine compose)
    float4 s = make_float4(0.f, 0.f, 0.f, 0.f);
    #pragma unroll 4
    for (int cc = 0; cc < c2; cc++) {
        const size_t idx = ((size_t)b * CH2 + cc) * D_ + d;
        const float4 A = *reinterpret_cast<const float4*>(&g_A[idx]);
        const float4 U = *reinterpret_cast<const float4*>(&g_U[idx]);
        s.x = fmaf(A.x, s.x, U.x);
        s.y = fmaf(A.y, s.y, U.y);
        s.z = fmaf(A.z, s.z, U.z);
        s.w = fmaf(A.w, s.w, U.w);
    }

    const size_t base = ((size_t)b * K_ + (size_t)c2 * T2) * D_ + d;
    const uint2* lam2 = reinterpret_cast<const uint2*>(g_lam16 + base);
    const uint2* x2 = reinterpret_cast<const uint2*>(g_xh + base);
    float4* y4 = reinterpret_cast<float4*>(ys + base);
    #pragma unroll 8
    for (int t = 0; t < T2; t++) {
        const uint2 lraw = lam2[(size_t)t * (D_ / 4)];
        const uint2 xraw = x2[(size_t)t * (D_ / 4)];
        const float2 l01 = __half22float2(*reinterpret_cast<const __half2*>(&lraw.x));
        const float2 l23 = __half22float2(*reinterpret_cast<const __half2*>(&lraw.y));
        const float2 x01 = __half22float2(*reinterpret_cast<const __half2*>(&xraw.x));
        const float2 x23 = __half22float2(*reinterpret_cast<const __half2*>(&xraw.y));
        s.x = fmaf(l01.x, s.x - x01.x, x01.x);
        s.y = fmaf(l01.y, s.y - x01.y, x01.y);
        s.z = fmaf(l23.x, s.z - x23.x, x23.x);
        s.w = fmaf(l23.y, s.w - x23.y, x23.y);
        y4[(size_t)t * (D_ / 4)] = s;
    }
}

// ---------------------------------------------------------------------------
extern "C" void kernel_launch(void* const* d_in, const int* in_sizes, int n_in,
                              void* d_out, int out_size) {
    const float* x    = (const float*)d_in[0];  // [B, K, D]
    const float* W    = (const float*)d_in[1];  // [K, K]
    const float* bias = (const float*)d_in[2];  // [K]
    float* ys = (float*)d_out;                  // [B, K, D]

    static bool attr_set = false;
    if (!attr_set) {
        cudaFuncSetAttribute(gemm_sigmoid_kernel,
                             cudaFuncAttributeMaxDynamicSharedMemorySize,
                             SMEM_TOTAL);
        attr_set = true;
    }

    const size_t total_conv = (size_t)K_ * K_ + (size_t)B_ * K_ * D_;  // 20M
    convert_all_kernel<<<(int)(total_conv / (256 * 4)), 256>>>(W, x);

    gemm_sigmoid_kernel<<<dim3(D_ / BN, K_ / BM, B_), 256, SMEM_TOTAL>>>(bias);

    scan_pass3<<<dim3(CH2, 2, B_), 128>>>(ys);
}

// round 11
// speedup vs baseline: 1.1492x; 1.1492x over previous
#include <cuda_runtime.h>
#include <cuda_fp16.h>
#include <cstdint>
#include <math.h>

// ---------------------------------------------------------------------------
// Problem constants
// ---------------------------------------------------------------------------
static constexpr int B_ = 8;
static constexpr int K_ = 2048;   // time / contraction dim
static constexpr int D_ = 1024;   // channel dim
static constexpr int CH2 = 32;    // half-chunks (T2 = 64 steps each)
static constexpr int T2 = K_ / CH2;  // 64

// GEMM tiling: C[t, d] = sum_k W[t,k] * x[k,d]   per batch, split-K=2
static constexpr int BM = 128;   // t tile (= 2 half-chunks)
static constexpr int BN = 128;   // d tile
static constexpr int BK = 32;    // k per stage
static constexpr int KSPLIT = 2;
static constexpr int KHALF = K_ / KSPLIT;          // 1024
static constexpr int NSTAGE_IT = KHALF / BK;       // 32
static constexpr int NSTAGES = 4;                  // pipeline depth
static constexpr int NTILES = B_ * (K_ / BM) * (D_ / BN);  // 1024

// smem strides (bytes), padded for conflict-free ldmatrix
static constexpr int W_STRIDE = 80;    // 32 fp16 = 64B + 16B pad
static constexpr int X_STRIDE = 272;   // 128 fp16 = 256B + 16B pad
static constexpr int W_TILE_B = BM * W_STRIDE;        // 10240
static constexpr int X_TILE_B = BK * X_STRIDE;        // 8704
static constexpr int STAGE_B = W_TILE_B + X_TILE_B;   // 18944
static constexpr int SMEM_TOTAL = NSTAGES * STAGE_B;  // 75776

// epilogue smem reuse: lam tile [128][136] fp16 (272B rows, 16B-aligned)
static constexpr int LAM_STRIDE = 136;                 // halves
static constexpr int LAM_BYTES = BM * LAM_STRIDE * 2;  // 34816
static_assert(LAM_BYTES <= SMEM_TOTAL, "epilogue fits");

// ---------------------------------------------------------------------------
// Device scratch (no cudaMalloc allowed)
// ---------------------------------------------------------------------------
__device__ __align__(256) __half g_Wh[(size_t)K_ * K_];
__device__ __align__(256) __half g_xh[(size_t)B_ * K_ * D_];
__device__ __align__(256) __half g_lam16[(size_t)B_ * K_ * D_];
__device__ __align__(256) float g_A[(size_t)B_ * CH2 * D_];   // half-chunk prod
__device__ __align__(256) float g_U[(size_t)B_ * CH2 * D_];   // half-chunk off
__device__ __align__(256) float g_part[(size_t)NTILES * KSPLIT * BM * BN];
__device__ int g_ticket[NTILES];   // zero-init; reset by finisher each call

// ---------------------------------------------------------------------------
// PTX helpers (baseline ISA only — target sm_103 has no 'a' features)
// ---------------------------------------------------------------------------
__device__ __forceinline__ uint32_t smem_u32(const void* p) {
    uint32_t a;
    asm("{ .reg .u64 t; cvta.to.shared.u64 t, %1; cvt.u32.u64 %0, t; }"
        : "=r"(a) : "l"(p));
    return a;
}

__device__ __forceinline__ void cp_async16(uint32_t dst, const void* src) {
    asm volatile("cp.async.cg.shared.global [%0], [%1], 16;"
                 :: "r"(dst), "l"(src));
}

__device__ __forceinline__ void ldm_x4(uint32_t* r, uint32_t addr) {
    asm volatile("ldmatrix.sync.aligned.m8n8.x4.shared.b16 {%0,%1,%2,%3}, [%4];"
                 : "=r"(r[0]), "=r"(r[1]), "=r"(r[2]), "=r"(r[3]) : "r"(addr));
}

__device__ __forceinline__ void ldm_x4_t(uint32_t* r, uint32_t addr) {
    asm volatile("ldmatrix.sync.aligned.m8n8.x4.trans.shared.b16 {%0,%1,%2,%3}, [%4];"
                 : "=r"(r[0]), "=r"(r[1]), "=r"(r[2]), "=r"(r[3]) : "r"(addr));
}

__device__ __forceinline__ void mma_f16(float* c, const uint32_t* a,
                                        const uint32_t b0, const uint32_t b1) {
    asm volatile(
        "mma.sync.aligned.m16n8k16.row.col.f32.f16.f16.f32 "
        "{%0,%1,%2,%3}, {%4,%5,%6,%7}, {%8,%9}, {%0,%1,%2,%3};"
        : "+f"(c[0]), "+f"(c[1]), "+f"(c[2]), "+f"(c[3])
        : "r"(a[0]), "r"(a[1]), "r"(a[2]), "r"(a[3]), "r"(b0), "r"(b1));
}

// ---------------------------------------------------------------------------
// Fused converter: fp32 -> fp16 for W (4M elems) then x (16M elems)
// ---------------------------------------------------------------------------
__global__ void convert_all_kernel(const float* __restrict__ W,
                                   const float* __restrict__ x) {
    const size_t gi = ((size_t)blockIdx.x * blockDim.x + threadIdx.x) * 4;
    const size_t WN = (size_t)K_ * K_;
    const float* src;
    __half* dst;
    size_t i;
    if (gi < WN) {
        src = W; dst = g_Wh; i = gi;
    } else {
        src = x; dst = g_xh; i = gi - WN;
    }
    float4 v = *reinterpret_cast<const float4*>(src + i);
    __half h[4];
    h[0] = __float2half(v.x); h[1] = __float2half(v.y);
    h[2] = __float2half(v.z); h[3] = __float2half(v.w);
    *reinterpret_cast<uint2*>(dst + i) = *reinterpret_cast<uint2*>(h);
}

// ---------------------------------------------------------------------------
// Split-K GEMM + ticketed combine + sigmoid + fused half-chunk summaries
// ---------------------------------------------------------------------------
__device__ __forceinline__ void load_stage(uint32_t sbase,
                                           const __half* Wp,
                                           const __half* xp,
                                           int k0, int tid) {
    #pragma unroll
    for (int u = tid; u < 512; u += 256) {
        const int row = u >> 2, seg = u & 3;
        const uint32_t off = (uint32_t)(row * W_STRIDE + seg * 16);
        cp_async16(sbase + off, Wp + (size_t)row * K_ + k0 + seg * 8);
    }
    #pragma unroll
    for (int u = tid; u < 512; u += 256) {
        const int row = u >> 4, seg = u & 15;
        const uint32_t off = (uint32_t)(row * X_STRIDE + seg * 16);
        cp_async16(sbase + W_TILE_B + off,
                   xp + (size_t)(k0 + row) * D_ + seg * 8);
    }
    asm volatile("cp.async.commit_group;" ::: "memory");
}

__global__ __launch_bounds__(256, 2)
void gemm_sigmoid_kernel(const float* __restrict__ bias) {
    extern __shared__ char smem[];
    __shared__ int s_flag;
    const uint32_t sb = smem_u32(smem);
    const int tid = threadIdx.x;
    const int lane = tid & 31;
    const int warp = tid >> 5;
    const int wm = warp >> 2;          // 0..1  (64 rows each)
    const int wn = warp & 3;           // 0..3  (32 cols each)

    const int dblk = blockIdx.x >> 1;        // 0..7
    const int khalf = blockIdx.x & 1;        // 0..1 (adjacent pairs)
    const int d0 = dblk * BN;
    const int t0 = blockIdx.y * BM;
    const int b = blockIdx.z;
    const int kbase = khalf * KHALF;
    const int tile = (b * (K_ / BM) + blockIdx.y) * (D_ / BN) + dblk;

    const __half* Wp = g_Wh + (size_t)t0 * K_;
    const __half* xp = g_xh + (size_t)b * K_ * D_ + d0;

    float acc[4][4][4];
    #pragma unroll
    for (int i = 0; i < 4; i++)
        #pragma unroll
        for (int j = 0; j < 4; j++)
            #pragma unroll
            for (int q = 0; q < 4; q++) acc[i][j][q] = 0.0f;

    const int a_row_in = (lane & 15);
    const int a_kseg = (lane >> 4);
    const int b_krow = (lane & 15);
    const int b_nseg = (lane >> 4);

    #pragma unroll
    for (int p = 0; p < NSTAGES - 1; p++)
        load_stage(sb + p * STAGE_B, Wp, xp, kbase + p * BK, tid);

    for (int c = 0; c < NSTAGE_IT; c++) {
        asm volatile("cp.async.wait_group %0;" :: "n"(NSTAGES - 2) : "memory");
        __syncthreads();

        if (c + NSTAGES - 1 < NSTAGE_IT)
            load_stage(sb + ((c + NSTAGES - 1) % NSTAGES) * STAGE_B,
                       Wp, xp, kbase + (c + NSTAGES - 1) * BK, tid);
        else
            asm volatile("cp.async.commit_group;" ::: "memory");

        const uint32_t st = sb + (c % NSTAGES) * STAGE_B;
        const uint32_t sW = st;
        const uint32_t sX = st + W_TILE_B;

        #pragma unroll
        for (int kk = 0; kk < 2; kk++) {
            uint32_t af[4][4];
            #pragma unroll
            for (int i = 0; i < 4; i++) {
                const uint32_t aoff =
                    (uint32_t)((wm * 64 + i * 16 + a_row_in) * W_STRIDE +
                               kk * 32 + a_kseg * 16);
                ldm_x4(af[i], sW + aoff);
            }
            uint32_t bf[2][4];
            #pragma unroll
            for (int j = 0; j < 2; j++) {
                const uint32_t boff =
                    (uint32_t)((kk * 16 + b_krow) * X_STRIDE +
                               (wn * 32 + j * 16 + b_nseg * 8) * 2);
                ldm_x4_t(bf[j], sX + boff);
            }
            #pragma unroll
            for (int i = 0; i < 4; i++) {
                #pragma unroll
                for (int j2 = 0; j2 < 4; j2++) {
                    const int jp = j2 >> 1, h = (j2 & 1) * 2;
                    mma_f16(acc[i][j2], af[i], bf[jp][h], bf[jp][h + 1]);
                }
            }
        }
    }

    asm volatile("cp.async.wait_group 0;" ::: "memory");

    // ---- Split-K combine: store own partial (coalesced), take a ticket ----
    {
        float* pp = g_part + ((size_t)(tile * KSPLIT + khalf)) * (BM * BN);
        int idx = 0;
        #pragma unroll
        for (int i = 0; i < 4; i++)
            #pragma unroll
            for (int j = 0; j < 4; j++) {
                float4 v = make_float4(acc[i][j][0], acc[i][j][1],
                                       acc[i][j][2], acc[i][j][3]);
                *reinterpret_cast<float4*>(&pp[idx * 1024 + tid * 4]) = v;
                idx++;
            }
    }
    __threadfence();
    __syncthreads();
    if (tid == 0) s_flag = atomicAdd(&g_ticket[tile], 1);
    __syncthreads();
    if (s_flag == 0) return;          // first finisher: partial published, done
    __threadfence();                  // acquire: peer's partial now visible

    // second finisher: add peer partial
    {
        const float* qq = g_part +
            ((size_t)(tile * KSPLIT + (khalf ^ 1))) * (BM * BN);
        int idx = 0;
        #pragma unroll
        for (int i = 0; i < 4; i++)
            #pragma unroll
            for (int j = 0; j < 4; j++) {
                const float4 v = *reinterpret_cast<const float4*>(
                    &qq[idx * 1024 + tid * 4]);
                acc[i][j][0] += v.x;
                acc[i][j][1] += v.y;
                acc[i][j][2] += v.z;
                acc[i][j][3] += v.w;
                idx++;
            }
    }
    if (tid == 0) g_ticket[tile] = 0;  // reset for next graph replay

    // ---- Epilogue phase 1: bias + sigmoid -> fp16 lam tile in smem ----
    __half* lamS = reinterpret_cast<__half*>(smem);          // [128][136]
    const int gr = lane >> 2;
    const int gc = (lane & 3) * 2;
    #pragma unroll
    for (int i = 0; i < 4; i++) {
        const int tr0 = wm * 64 + i * 16 + gr;
        const float bz0 = __ldg(&bias[t0 + tr0]);
        const float bz1 = __ldg(&bias[t0 + tr0 + 8]);
        #pragma unroll
        for (int j2 = 0; j2 < 4; j2++) {
            const int dc = wn * 32 + j2 * 8 + gc;
            __half2 h0, h1;
            h0.x = __float2half(1.0f / (1.0f + __expf(-(acc[i][j2][0] + bz0))));
            h0.y = __float2half(1.0f / (1.0f + __expf(-(acc[i][j2][1] + bz0))));
            h1.x = __float2half(1.0f / (1.0f + __expf(-(acc[i][j2][2] + bz1))));
            h1.y = __float2half(1.0f / (1.0f + __expf(-(acc[i][j2][3] + bz1))));
            *reinterpret_cast<__half2*>(&lamS[tr0 * LAM_STRIDE + dc]) = h0;
            *reinterpret_cast<__half2*>(&lamS[(tr0 + 8) * LAM_STRIDE + dc]) = h1;
        }
    }
    __syncthreads();

    // ---- Epilogue phase 2a: coalesced uint4 store of fp16 lam to gmem ----
    __half* lamB = g_lam16 + ((size_t)b * K_ + t0) * D_ + d0;
    #pragma unroll
    for (int u = tid; u < BM * (BN / 8); u += 256) {  // 2048 uint4
        const int row = u >> 4;          // 0..127
        const int col8 = (u & 15) * 8;   // 0..120
        const uint4 v = *reinterpret_cast<const uint4*>(
            &lamS[row * LAM_STRIDE + col8]);
        *reinterpret_cast<uint4*>(&lamB[(size_t)row * D_ + col8]) = v;
    }

    // ---- Epilogue phase 2b: per-half affine summaries (quantized lam+x) ----
    {
        const int half = tid >> 7;       // 0: t 0..63, 1: t 64..127
        const int dc = tid & 127;
        const __half* xcol = g_xh +
            ((size_t)b * K_ + t0 + half * 64) * D_ + d0 + dc;
        float A = 1.0f, U = 0.0f;
        #pragma unroll 8
        for (int tt = 0; tt < 64; tt++) {
            const float l = __half2float(lamS[(half * 64 + tt) * LAM_STRIDE + dc]);
            const float xv = __half2float(xcol[(size_t)tt * D_]);
            U = fmaf(l, U - xv, xv);
            A *= l;
        }
        const int c2 = blockIdx.y * 2 + half;   // half-chunk index 0..31
        const size_t idx = ((size_t)b * CH2 + c2) * D_ + d0 + dc;
        g_A[idx] = A;
        g_U[idx] = U;
    }
}

// ---------------------------------------------------------------------------
// Scan pass 3: per (b, half-chunk, d-half) block; carry computed in-register
// from half-chunk summaries. 128 threads x float4 over 512 d each.
// ---------------------------------------------------------------------------
__global__ __launch_bounds__(128)
void scan_pass3(float* __restrict__ ys) {
    const int c2 = CH2 - 1 - blockIdx.x;  // heavy blocks first
    const int b = blockIdx.z;
    const int d = blockIdx.y * 512 + threadIdx.x * 4;

    float4 s = make_float4(0.f, 0.f, 0.f, 0.f);
    #pragma unroll 4
    for (int cc = 0; cc < c2; cc++) {
        const size_t idx = ((size_t)b * CH2 + cc) * D_ + d;
        const float4 A = *reinterpret_cast<const float4*>(&g_A[idx]);
        const float4 U = *reinterpret_cast<const float4*>(&g_U[idx]);
        s.x = fmaf(A.x, s.x, U.x);
        s.y = fmaf(A.y, s.y, U.y);
        s.z = fmaf(A.z, s.z, U.z);
        s.w = fmaf(A.w, s.w, U.w);
    }

    const size_t base = ((size_t)b * K_ + (size_t)c2 * T2) * D_ + d;
    const uint2* lam2 = reinterpret_cast<const uint2*>(g_lam16 + base);
    const uint2* x2 = reinterpret_cast<const uint2*>(g_xh + base);
    float4* y4 = reinterpret_cast<float4*>(ys + base);
    #pragma unroll 8
    for (int t = 0; t < T2; t++) {
        const uint2 lraw = lam2[(size_t)t * (D_ / 4)];
        const uint2 xraw = x2[(size_t)t * (D_ / 4)];
        const float2 l01 = __half22float2(*reinterpret_cast<const __half2*>(&lraw.x));
        const float2 l23 = __half22float2(*reinterpret_cast<const __half2*>(&lraw.y));
        const float2 x01 = __half22float2(*reinterpret_cast<const __half2*>(&xraw.x));
        const float2 x23 = __half22float2(*reinterpret_cast<const __half2*>(&xraw.y));
        s.x = fmaf(l01.x, s.x - x01.x, x01.x);
        s.y = fmaf(l01.y, s.y - x01.y, x01.y);
        s.z = fmaf(l23.x, s.z - x23.x, x23.x);
        s.w = fmaf(l23.y, s.w - x23.y, x23.y);
        y4[(size_t)t * (D_ / 4)] = s;
    }
}

// ---------------------------------------------------------------------------
extern "C" void kernel_launch(void* const* d_in, const int* in_sizes, int n_in,
                              void* d_out, int out_size) {
    const float* x    = (const float*)d_in[0];  // [B, K, D]
    const float* W    = (const float*)d_in[1];  // [K, K]
    const float* bias = (const float*)d_in[2];  // [K]
    float* ys = (float*)d_out;                  // [B, K, D]

    static bool attr_set = false;
    if (!attr_set) {
        cudaFuncSetAttribute(gemm_sigmoid_kernel,
                             cudaFuncAttributeMaxDynamicSharedMemorySize,
                             SMEM_TOTAL);
        attr_set = true;
    }

    const size_t total_conv = (size_t)K_ * K_ + (size_t)B_ * K_ * D_;  // 20M
    convert_all_kernel<<<(int)(total_conv / (256 * 4)), 256>>>(W, x);

    // grid.x = dblk*2 + khalf (pairs adjacent -> co-scheduled, L2-hot combine)
    gemm_sigmoid_kernel<<<dim3((D_ / BN) * KSPLIT, K_ / BM, B_), 256,
                          SMEM_TOTAL>>>(bias);

    scan_pass3<<<dim3(CH2, 2, B_), 128>>>(ys);
}

// round 12
// speedup vs baseline: 1.3404x; 1.1664x over previous
#include <cuda_runtime.h>
#include <cuda_fp16.h>
#include <cstdint>
#include <math.h>

// ---------------------------------------------------------------------------
// Problem constants
// ---------------------------------------------------------------------------
static constexpr int B_ = 8;
static constexpr int K_ = 2048;   // time / contraction dim
static constexpr int D_ = 1024;   // channel dim
static constexpr int CH2 = 32;    // half-chunks (T2 = 64 steps each)
static constexpr int T2 = K_ / CH2;  // 64

// GEMM tiling: C[t, d] = sum_k W[t,k] * x[k,d]   per batch
static constexpr int BM = 128;   // t tile (= 2 half-chunks)
static constexpr int BN = 128;   // d tile
static constexpr int BK = 32;    // k per stage
static constexpr int NSTAGE_IT = K_ / BK;  // 64
static constexpr int NSTAGES = 4;          // pipeline depth

// smem strides (bytes), padded for conflict-free ldmatrix
static constexpr int W_STRIDE = 80;    // 32 fp16 = 64B + 16B pad
static constexpr int X_STRIDE = 272;   // 128 fp16 = 256B + 16B pad
static constexpr int W_TILE_B = BM * W_STRIDE;        // 10240
static constexpr int X_TILE_B = BK * X_STRIDE;        // 8704
static constexpr int STAGE_B = W_TILE_B + X_TILE_B;   // 18944
static constexpr int SMEM_TOTAL = NSTAGES * STAGE_B;  // 75776

// epilogue smem reuse: lam tile [128][136] fp16 (272B rows, 16B-aligned)
static constexpr int LAM_STRIDE = 136;                 // halves
static constexpr int LAM_BYTES = BM * LAM_STRIDE * 2;  // 34816
static_assert(LAM_BYTES <= SMEM_TOTAL, "epilogue fits");

// ---------------------------------------------------------------------------
// Device scratch (no cudaMalloc allowed)
// ---------------------------------------------------------------------------
__device__ __align__(256) __half g_Wh[(size_t)K_ * K_];
__device__ __align__(256) __half g_xh[(size_t)B_ * K_ * D_];
__device__ __align__(256) __half g_lam16[(size_t)B_ * K_ * D_];
__device__ __align__(256) float g_A[(size_t)B_ * CH2 * D_];   // half-chunk prod
__device__ __align__(256) float g_U[(size_t)B_ * CH2 * D_];   // half-chunk off

// ---------------------------------------------------------------------------
// PTX helpers (baseline ISA only — target sm_103 has no 'a' features)
// ---------------------------------------------------------------------------
__device__ __forceinline__ uint32_t smem_u32(const void* p) {
    uint32_t a;
    asm("{ .reg .u64 t; cvta.to.shared.u64 t, %1; cvt.u32.u64 %0, t; }"
        : "=r"(a) : "l"(p));
    return a;
}

__device__ __forceinline__ void cp_async16(uint32_t dst, const void* src) {
    asm volatile("cp.async.cg.shared.global [%0], [%1], 16;"
                 :: "r"(dst), "l"(src));
}

__device__ __forceinline__ void ldm_x4(uint32_t* r, uint32_t addr) {
    asm volatile("ldmatrix.sync.aligned.m8n8.x4.shared.b16 {%0,%1,%2,%3}, [%4];"
                 : "=r"(r[0]), "=r"(r[1]), "=r"(r[2]), "=r"(r[3]) : "r"(addr));
}

__device__ __forceinline__ void ldm_x4_t(uint32_t* r, uint32_t addr) {
    asm volatile("ldmatrix.sync.aligned.m8n8.x4.trans.shared.b16 {%0,%1,%2,%3}, [%4];"
                 : "=r"(r[0]), "=r"(r[1]), "=r"(r[2]), "=r"(r[3]) : "r"(addr));
}

__device__ __forceinline__ void mma_f16(float* c, const uint32_t* a,
                                        const uint32_t b0, const uint32_t b1) {
    asm volatile(
        "mma.sync.aligned.m16n8k16.row.col.f32.f16.f16.f32 "
        "{%0,%1,%2,%3}, {%4,%5,%6,%7}, {%8,%9}, {%0,%1,%2,%3};"
        : "+f"(c[0]), "+f"(c[1]), "+f"(c[2]), "+f"(c[3])
        : "r"(a[0]), "r"(a[1]), "r"(a[2]), "r"(a[3]), "r"(b0), "r"(b1));
}

// ---------------------------------------------------------------------------
// Fused converter: fp32 -> fp16, 8 elems/thread (W: 4M elems, x: 16M elems)
// Block covers 2048 elems; first 2048 blocks = W exactly, rest = x.
// ---------------------------------------------------------------------------
__global__ void convert_all_kernel(const float* __restrict__ W,
                                   const float* __restrict__ x) {
    const size_t gi = ((size_t)blockIdx.x * blockDim.x + threadIdx.x) * 8;
    const size_t WN = (size_t)K_ * K_;
    const float* src;
    __half* dst;
    size_t i;
    if (gi < WN) {
        src = W; dst = g_Wh; i = gi;
    } else {
        src = x; dst = g_xh; i = gi - WN;
    }
    const float4 v0 = *reinterpret_cast<const float4*>(src + i);
    const float4 v1 = *reinterpret_cast<const float4*>(src + i + 4);
    __half h[8];
    h[0] = __float2half(v0.x); h[1] = __float2half(v0.y);
    h[2] = __float2half(v0.z); h[3] = __float2half(v0.w);
    h[4] = __float2half(v1.x); h[5] = __float2half(v1.y);
    h[6] = __float2half(v1.z); h[7] = __float2half(v1.w);
    *reinterpret_cast<uint4*>(dst + i) = *reinterpret_cast<uint4*>(h);
}

// ---------------------------------------------------------------------------
// GEMM + sigmoid + fused half-chunk scan summaries (lam stored fp16)
// ---------------------------------------------------------------------------
__device__ __forceinline__ void load_stage(uint32_t sbase,
                                           const __half* Wp,
                                           const __half* xp,
                                           int k0, int tid) {
    #pragma unroll
    for (int u = tid; u < 512; u += 256) {
        const int row = u >> 2, seg = u & 3;
        const uint32_t off = (uint32_t)(row * W_STRIDE + seg * 16);
        cp_async16(sbase + off, Wp + (size_t)row * K_ + k0 + seg * 8);
    }
    #pragma unroll
    for (int u = tid; u < 512; u += 256) {
        const int row = u >> 4, seg = u & 15;
        const uint32_t off = (uint32_t)(row * X_STRIDE + seg * 16);
        cp_async16(sbase + W_TILE_B + off,
                   xp + (size_t)(k0 + row) * D_ + seg * 8);
    }
    asm volatile("cp.async.commit_group;" ::: "memory");
}

__global__ __launch_bounds__(256, 2)
void gemm_sigmoid_kernel(const float* __restrict__ bias) {
    extern __shared__ char smem[];
    const uint32_t sb = smem_u32(smem);
    const int tid = threadIdx.x;
    const int lane = tid & 31;
    const int warp = tid >> 5;
    const int wm = warp >> 2;          // 0..1  (64 rows each)
    const int wn = warp & 3;           // 0..3  (32 cols each)

    const int d0 = blockIdx.x * BN;
    const int t0 = blockIdx.y * BM;
    const int b = blockIdx.z;

    const __half* Wp = g_Wh + (size_t)t0 * K_;
    const __half* xp = g_xh + (size_t)b * K_ * D_ + d0;

    float acc[4][4][4];
    #pragma unroll
    for (int i = 0; i < 4; i++)
        #pragma unroll
        for (int j = 0; j < 4; j++)
            #pragma unroll
            for (int q = 0; q < 4; q++) acc[i][j][q] = 0.0f;

    const int a_row_in = (lane & 15);
    const int a_kseg = (lane >> 4);
    const int b_krow = (lane & 15);
    const int b_nseg = (lane >> 4);

    #pragma unroll
    for (int p = 0; p < NSTAGES - 1; p++)
        load_stage(sb + p * STAGE_B, Wp, xp, p * BK, tid);

    for (int c = 0; c < NSTAGE_IT; c++) {
        asm volatile("cp.async.wait_group %0;" :: "n"(NSTAGES - 2) : "memory");
        __syncthreads();

        if (c + NSTAGES - 1 < NSTAGE_IT)
            load_stage(sb + ((c + NSTAGES - 1) % NSTAGES) * STAGE_B,
                       Wp, xp, (c + NSTAGES - 1) * BK, tid);
        else
            asm volatile("cp.async.commit_group;" ::: "memory");

        const uint32_t st = sb + (c % NSTAGES) * STAGE_B;
        const uint32_t sW = st;
        const uint32_t sX = st + W_TILE_B;

        #pragma unroll
        for (int kk = 0; kk < 2; kk++) {
            uint32_t af[4][4];
            #pragma unroll
            for (int i = 0; i < 4; i++) {
                const uint32_t aoff =
                    (uint32_t)((wm * 64 + i * 16 + a_row_in) * W_STRIDE +
                               kk * 32 + a_kseg * 16);
                ldm_x4(af[i], sW + aoff);
            }
            uint32_t bf[2][4];
            #pragma unroll
            for (int j = 0; j < 2; j++) {
                const uint32_t boff =
                    (uint32_t)((kk * 16 + b_krow) * X_STRIDE +
                               (wn * 32 + j * 16 + b_nseg * 8) * 2);
                ldm_x4_t(bf[j], sX + boff);
            }
            #pragma unroll
            for (int i = 0; i < 4; i++) {
                #pragma unroll
                for (int j2 = 0; j2 < 4; j2++) {
                    const int jp = j2 >> 1, h = (j2 & 1) * 2;
                    mma_f16(acc[i][j2], af[i], bf[jp][h], bf[jp][h + 1]);
                }
            }
        }
    }

    // drain async engine before smem reuse
    asm volatile("cp.async.wait_group 0;" ::: "memory");
    __syncthreads();

    // ---- Epilogue phase 1: bias + sigmoid -> fp16 lam tile in smem ----
    __half* lamS = reinterpret_cast<__half*>(smem);          // [128][136]
    const int gr = lane >> 2;
    const int gc = (lane & 3) * 2;
    #pragma unroll
    for (int i = 0; i < 4; i++) {
        const int tr0 = wm * 64 + i * 16 + gr;
        const float bz0 = __ldg(&bias[t0 + tr0]);
        const float bz1 = __ldg(&bias[t0 + tr0 + 8]);
        #pragma unroll
        for (int j2 = 0; j2 < 4; j2++) {
            const int dc = wn * 32 + j2 * 8 + gc;
            __half2 h0, h1;
            h0.x = __float2half(1.0f / (1.0f + __expf(-(acc[i][j2][0] + bz0))));
            h0.y = __float2half(1.0f / (1.0f + __expf(-(acc[i][j2][1] + bz0))));
            h1.x = __float2half(1.0f / (1.0f + __expf(-(acc[i][j2][2] + bz1))));
            h1.y = __float2half(1.0f / (1.0f + __expf(-(acc[i][j2][3] + bz1))));
            *reinterpret_cast<__half2*>(&lamS[tr0 * LAM_STRIDE + dc]) = h0;
            *reinterpret_cast<__half2*>(&lamS[(tr0 + 8) * LAM_STRIDE + dc]) = h1;
        }
    }
    __syncthreads();

    // ---- Epilogue phase 2a: coalesced uint4 store of fp16 lam to gmem ----
    __half* lamB = g_lam16 + ((size_t)b * K_ + t0) * D_ + d0;
    #pragma unroll
    for (int u = tid; u < BM * (BN / 8); u += 256) {  // 2048 uint4
        const int row = u >> 4;          // 0..127
        const int col8 = (u & 15) * 8;   // 0..120
        const uint4 v = *reinterpret_cast<const uint4*>(
            &lamS[row * LAM_STRIDE + col8]);
        *reinterpret_cast<uint4*>(&lamB[(size_t)row * D_ + col8]) = v;
    }

    // ---- Epilogue phase 2b: per-half affine summaries (quantized lam+x) ----
    {
        const int half = tid >> 7;       // 0: t 0..63, 1: t 64..127
        const int dc = tid & 127;
        const __half* xcol = g_xh +
            ((size_t)b * K_ + t0 + half * 64) * D_ + d0 + dc;
        float A = 1.0f, U = 0.0f;
        #pragma unroll 8
        for (int tt = 0; tt < 64; tt++) {
            const float l = __half2float(lamS[(half * 64 + tt) * LAM_STRIDE + dc]);
            const float xv = __half2float(xcol[(size_t)tt * D_]);
            U = fmaf(l, U - xv, xv);
            A *= l;
        }
        const int c2 = blockIdx.y * 2 + half;   // half-chunk index 0..31
        const size_t idx = ((size_t)b * CH2 + c2) * D_ + d0 + dc;
        g_A[idx] = A;
        g_U[idx] = U;
    }
}

// ---------------------------------------------------------------------------
// Scan pass 3: per (b, half-chunk, d-half) block; carry computed in-register
// from half-chunk summaries. 128 threads x float4 over 512 d each.
// fp16 x + fp16 lam reads, unroll-8 for MLP. Heavy blocks launch first.
// ---------------------------------------------------------------------------
__global__ __launch_bounds__(128)
void scan_pass3(float* __restrict__ ys) {
    const int c2 = CH2 - 1 - blockIdx.x;  // heavy blocks first
    const int b = blockIdx.z;
    const int d = blockIdx.y * 512 + threadIdx.x * 4;

    // carry = prefix of (A,U) over half-chunks < c2 (affine compose)
    float4 s = make_float4(0.f, 0.f, 0.f, 0.f);
    #pragma unroll 4
    for (int cc = 0; cc < c2; cc++) {
        const size_t idx = ((size_t)b * CH2 + cc) * D_ + d;
        const float4 A = *reinterpret_cast<const float4*>(&g_A[idx]);
        const float4 U = *reinterpret_cast<const float4*>(&g_U[idx]);
        s.x = fmaf(A.x, s.x, U.x);
        s.y = fmaf(A.y, s.y, U.y);
        s.z = fmaf(A.z, s.z, U.z);
        s.w = fmaf(A.w, s.w, U.w);
    }

    const size_t base = ((size_t)b * K_ + (size_t)c2 * T2) * D_ + d;
    const uint2* lam2 = reinterpret_cast<const uint2*>(g_lam16 + base);
    const uint2* x2 = reinterpret_cast<const uint2*>(g_xh + base);
    float4* y4 = reinterpret_cast<float4*>(ys + base);
    #pragma unroll 8
    for (int t = 0; t < T2; t++) {
        const uint2 lraw = lam2[(size_t)t * (D_ / 4)];
        const uint2 xraw = x2[(size_t)t * (D_ / 4)];
        const float2 l01 = __half22float2(*reinterpret_cast<const __half2*>(&lraw.x));
        const float2 l23 = __half22float2(*reinterpret_cast<const __half2*>(&lraw.y));
        const float2 x01 = __half22float2(*reinterpret_cast<const __half2*>(&xraw.x));
        const float2 x23 = __half22float2(*reinterpret_cast<const __half2*>(&xraw.y));
        s.x = fmaf(l01.x, s.x - x01.x, x01.x);
        s.y = fmaf(l01.y, s.y - x01.y, x01.y);
        s.z = fmaf(l23.x, s.z - x23.x, x23.x);
        s.w = fmaf(l23.y, s.w - x23.y, x23.y);
        y4[(size_t)t * (D_ / 4)] = s;
    }
}

// ---------------------------------------------------------------------------
extern "C" void kernel_launch(void* const* d_in, const int* in_sizes, int n_in,
                              void* d_out, int out_size) {
    const float* x    = (const float*)d_in[0];  // [B, K, D]
    const float* W    = (const float*)d_in[1];  // [K, K]
    const float* bias = (const float*)d_in[2];  // [K]
    float* ys = (float*)d_out;                  // [B, K, D]

    static bool attr_set = false;
    if (!attr_set) {
        cudaFuncSetAttribute(gemm_sigmoid_kernel,
                             cudaFuncAttributeMaxDynamicSharedMemorySize,
                             SMEM_TOTAL);
        attr_set = true;
    }

    const size_t total_conv = (size_t)K_ * K_ + (size_t)B_ * K_ * D_;  // 20M
    convert_all_kernel<<<(int)(total_conv / (256 * 8)), 256>>>(W, x);

    gemm_sigmoid_kernel<<<dim3(D_ / BN, K_ / BM, B_), 256, SMEM_TOTAL>>>(bias);

    scan_pass3<<<dim3(CH2, 2, B_), 128>>>(ys);
}